// round 13
// baseline (speedup 1.0000x reference)
#include <cuda_runtime.h>
#include <cuda_bf16.h>
#include <cuda_fp16.h>
#include <cstdint>

// ---------------- problem constants ----------------
#define NS    4096      // B*T
#define SDIM  512
#define AG    16
#define ACT   20
#define MOUT  320
#define EDIM  64
#define COLS  1216      // 1024 w1 + 64 b1 + 64 wf + 64 zv
#define COLSP 1280      // padded to 8*160

#define LOG2E 1.4426950408889634f
#define LN2   0.6931471805599453f

// ---------------- device scratch ----------------
__device__ float   g_C[NS * COLS];
__device__ __half  g_B0[COLSP * SDIM];       // fp16(W)
__device__ float   g_bias[COLSP];

// ---------------- PTX helpers (sm_100-safe) ----------------
__device__ __forceinline__ uint32_t smem_u32(const void* p) {
    uint32_t a;
    asm("{ .reg .u64 t; cvta.to.shared.u64 t, %1; cvt.u32.u64 %0, t; }" : "=r"(a) : "l"(p));
    return a;
}
__device__ __forceinline__ void cp16(uint32_t dst, const void* src) {
    asm volatile("cp.async.cg.shared.global [%0], [%1], 16;" :: "r"(dst), "l"(src));
}
#define CP_COMMIT() asm volatile("cp.async.commit_group;" ::: "memory")
#define CP_WAIT2()  asm volatile("cp.async.wait_group 2;" ::: "memory")

__device__ __forceinline__ void ldm_x4(uint32_t* r, uint32_t addr) {
    asm volatile("ldmatrix.sync.aligned.m8n8.x4.shared.b16 {%0,%1,%2,%3}, [%4];"
        : "=r"(r[0]), "=r"(r[1]), "=r"(r[2]), "=r"(r[3]) : "r"(addr));
}
__device__ __forceinline__ void ldm_x2(uint32_t* r, uint32_t addr) {
    asm volatile("ldmatrix.sync.aligned.m8n8.x2.shared.b16 {%0,%1}, [%2];"
        : "=r"(r[0]), "=r"(r[1]) : "r"(addr));
}
__device__ __forceinline__ void mma_f16(float* c, const uint32_t* a, uint32_t b0, uint32_t b1) {
    asm volatile(
        "mma.sync.aligned.m16n8k16.row.col.f32.f16.f16.f32 "
        "{%0,%1,%2,%3}, {%4,%5,%6,%7}, {%8,%9}, {%0,%1,%2,%3};"
        : "+f"(c[0]), "+f"(c[1]), "+f"(c[2]), "+f"(c[3])
        : "r"(a[0]), "r"(a[1]), "r"(a[2]), "r"(a[3]), "r"(b0), "r"(b1));
}

__device__ __forceinline__ uint32_t pack2h(float a, float b) {
    __half2 t(__float2half_rn(a), __float2half_rn(b));
    return *(uint32_t*)&t;
}

// ============================================================================
// Kernel 0: W -> fp16; concat bias. (A conversion folded into the GEMM)
// ============================================================================
#define CONV_BBLK 160
#define CONV_GRID (CONV_BBLK + 1)

__global__ void __launch_bounds__(256)
convert_split(const float* __restrict__ W_h1, const float* __restrict__ b_h1,
              const float* __restrict__ W_b1, const float* __restrict__ b_b1,
              const float* __restrict__ W_hf, const float* __restrict__ b_hf,
              const float* __restrict__ W_v1, const float* __restrict__ b_v1)
{
    const int blk = blockIdx.x;
    const int tid = threadIdx.x;

    if (blk < CONV_BBLK) {
        int base = blk * 1024 + tid;
        float4 v[4];
        #pragma unroll
        for (int k = 0; k < 4; k++) {
            int q = base + k * 256;
            int row = q >> 7;            // 128 quads per 512-wide row
            int cq  = q & 127;
            if (row < 1024)      v[k] = ((const float4*)(W_h1 + (size_t)row * SDIM))[cq];
            else if (row < 1088) v[k] = ((const float4*)(W_b1 + (size_t)(row - 1024) * SDIM))[cq];
            else if (row < 1152) v[k] = ((const float4*)(W_hf + (size_t)(row - 1088) * SDIM))[cq];
            else if (row < 1216) v[k] = ((const float4*)(W_v1 + (size_t)(row - 1152) * SDIM))[cq];
            else                 v[k] = make_float4(0.f, 0.f, 0.f, 0.f);
        }
        #pragma unroll
        for (int k = 0; k < 4; k++) {
            uint2 p;
            p.x = pack2h(v[k].x, v[k].y);  p.y = pack2h(v[k].z, v[k].w);
            ((uint2*)g_B0)[base + k * 256] = p;
        }
    } else {
        #pragma unroll
        for (int t = 0; t < 5; t++) {
            int c = t * 256 + tid;
            if (c < COLSP) {
                float b = 0.f;
                if (c < 1024)      b = b_h1[c];
                else if (c < 1088) b = b_b1[c - 1024];
                else if (c < 1152) b = b_hf[c - 1088];
                else if (c < 1216) b = b_v1[c - 1152];
                g_bias[c] = b;
            }
        }
    }
}

// ============================================================================
// Kernel 1: HMMA fp16 GEMM with inline A conversion: C = fp16(state)*B0 + bias
// Tile 128(M) x 160(N) x 32(K). grid (8, 32) = 256 CTAs, 2 CTAs/SM.
// A path: fp32 LDG (iter kt loads stage kt+3) -> regs -> cvt+STS (iter kt
//   stores stage kt+2) into the 4-deep fp16 A ring. Writer at kt targets slot
//   (kt+2)%4; laggard readers (skew<=1 via the per-iter barrier) touch slot
//   (kt-1)%4 -- distance 3 mod 4, no aliasing (same proof as the B ring).
// B path: cp.async 4-stage, lookahead 2 (unchanged from R8).
// ============================================================================
#define ROWB   80
#define MATBA  (128 * ROWB)             // 10240 B (A fp16 ring slot)
#define MATBB  (160 * ROWB)             // 12800 B (B ring slot)
#define STAGEB (MATBA + MATBB)          // 23040 B
#define NSTAGE 4
#define GEMM_SMEM (NSTAGE * STAGEB)     // 92160 B
#define NBCHUNK (160 * 4)               // 640 16B-chunks of B per stage

__device__ __forceinline__ void load_stageB(uint32_t sb, int tid, int rowB, int kt) {
    #pragma unroll
    for (int t = 0; t < 3; t++) {
        int id = tid + t * 256;          // 0..767
        if (id < NBCHUNK) {
            int r = id >> 2, c = id & 3;
            cp16(sb + MATBA + (uint32_t)(r * ROWB + c * 16),
                 (const char*)g_B0 + ((size_t)(rowB + r) * SDIM + kt) * 2 + c * 16);
        }
    }
}

__global__ void __launch_bounds__(256, 2)
gemm_tc(const float* __restrict__ state)
{
    extern __shared__ char smem[];
    const uint32_t sbase = smem_u32(smem);
    const int tid  = threadIdx.x;
    const int wid  = tid >> 5;
    const int lane = tid & 31;
    const int cb   = blockIdx.x;   // 0..7
    const int rb   = blockIdx.y;   // 0..31

    const int warp_m = wid >> 2;
    const int warp_n = wid & 3;
    const int rowA = rb * 128;
    const int rowB = cb * 160;

    float c[4][5][4];
    #pragma unroll
    for (int i = 0; i < 4; i++)
        #pragma unroll
        for (int j = 0; j < 5; j++)
            #pragma unroll
            for (int q = 0; q < 4; q++)
                c[i][j][q] = 0.f;

    // ---- A conversion path state ----
    const int ar = tid >> 1;            // A row 0..127
    const int ah = tid & 1;             // k-half (16 floats)
    const float* aSrcBase = state + (size_t)(rowA + ar) * SDIM + ah * 16;
    char* aDstBase = smem + ar * ROWB + ah * 32;
    float4 aReg[4];

    #define LDG_A(kt32) do { \
        const float* _p = aSrcBase + (kt32); \
        aReg[0] = *(const float4*)(_p); \
        aReg[1] = *(const float4*)(_p + 4); \
        aReg[2] = *(const float4*)(_p + 8); \
        aReg[3] = *(const float4*)(_p + 12); \
    } while (0)

    #define STS_A(slot) do { \
        uint4 _u0, _u1; \
        _u0.x = pack2h(aReg[0].x, aReg[0].y); _u0.y = pack2h(aReg[0].z, aReg[0].w); \
        _u0.z = pack2h(aReg[1].x, aReg[1].y); _u0.w = pack2h(aReg[1].z, aReg[1].w); \
        _u1.x = pack2h(aReg[2].x, aReg[2].y); _u1.y = pack2h(aReg[2].z, aReg[2].w); \
        _u1.z = pack2h(aReg[3].x, aReg[3].y); _u1.w = pack2h(aReg[3].z, aReg[3].w); \
        char* _d = aDstBase + (slot) * STAGEB; \
        *(uint4*)(_d)      = _u0; \
        *(uint4*)(_d + 16) = _u1; \
    } while (0)

    // ---- prologue ----
    LDG_A(0);   STS_A(0);
    LDG_A(32);  STS_A(1);
    LDG_A(64);                          // stage 2 held in regs (stored at iter 0)
    load_stageB(sbase + 0 * STAGEB, tid, rowB, 0);
    CP_COMMIT();
    load_stageB(sbase + 1 * STAGEB, tid, rowB, 32);
    CP_COMMIT();

    const uint32_t lrow  = (uint32_t)(lane & 15) * ROWB;
    const uint32_t lcol  = (uint32_t)(lane >> 4) * 16;
    const uint32_t lrow2 = (uint32_t)(lane & 7) * ROWB;
    const uint32_t lcol2 = (uint32_t)((lane >> 3) & 1) * 16;

    const int NK = SDIM / 32;   // 16
    for (int kt = 0; kt < NK; kt++) {
        if (kt + 2 < NK) STS_A((kt + 2) % NSTAGE);          // regs from iter kt-1
        if (kt + 3 < NK) LDG_A((kt + 3) * 32);              // for iter kt+1's STS
        if (kt + 2 < NK)
            load_stageB(sbase + ((kt + 2) % NSTAGE) * STAGEB, tid, rowB, (kt + 2) * 32);
        CP_COMMIT();
        CP_WAIT2();
        __syncthreads();

        const uint32_t st = sbase + (kt % NSTAGE) * STAGEB;
        const uint32_t aAddr   = st + lrow + lcol;
        const uint32_t bBase   = st + MATBA + (uint32_t)(warp_n * 40) * ROWB;
        const uint32_t bAddrX4 = bBase + lrow + lcol;
        const uint32_t bAddrX2 = bBase + 32 * ROWB + lrow2 + lcol2;

        #pragma unroll
        for (int kk = 0; kk < 2; kk++) {
            uint32_t a[4][4];
            #pragma unroll
            for (int mt = 0; mt < 4; mt++)
                ldm_x4(a[mt], aAddr + (uint32_t)((warp_m * 64 + mt * 16) * ROWB + kk * 32));

            uint32_t b4a[4], b4b[4], b2[2];
            ldm_x4(b4a, bAddrX4 + (uint32_t)(kk * 32));
            ldm_x4(b4b, bAddrX4 + (uint32_t)(16 * ROWB + kk * 32));
            ldm_x2(b2,  bAddrX2 + (uint32_t)(kk * 32));

            #pragma unroll
            for (int mt = 0; mt < 4; mt++) {
                mma_f16(c[mt][0], a[mt], b4a[0], b4a[2]);
                mma_f16(c[mt][1], a[mt], b4a[1], b4a[3]);
                mma_f16(c[mt][2], a[mt], b4b[0], b4b[2]);
                mma_f16(c[mt][3], a[mt], b4b[1], b4b[3]);
                mma_f16(c[mt][4], a[mt], b2[0],  b2[1]);
            }
        }
        // no trailing barrier (ring reuse distance 3 mod 4; see header)
    }

    // epilogue
    const int rbase = rb * 128 + warp_m * 64 + (lane >> 2);
    const int cbase = cb * 160 + warp_n * 40 + (lane & 3) * 2;
    #pragma unroll
    for (int nt = 0; nt < 5; nt++) {
        int col = cbase + nt * 8;
        if (col >= COLS) continue;
        float2 bias = *(const float2*)(g_bias + col);
        #pragma unroll
        for (int mt = 0; mt < 4; mt++) {
            int r0 = rbase + mt * 16;
            float2 v0, v1;
            v0.x = c[mt][nt][0] + bias.x; v0.y = c[mt][nt][1] + bias.y;
            v1.x = c[mt][nt][2] + bias.x; v1.y = c[mt][nt][3] + bias.y;
            *(float2*)(g_C + (size_t)r0 * COLS + col)       = v0;
            *(float2*)(g_C + (size_t)(r0 + 8) * COLS + col) = v1;
        }
    }
}

// ============================================================================
// Kernel 2: mixer (identical to R12). TWO warps per sample, packed-half2
// inner loop: xh = hfma2(dL2,wh,u2h); acc1h += hmax2*wfh; acc2h += exp2*wfh.
// u2/wf/v/swf and cross-lane reductions stay fp32.
// ============================================================================
__global__ void __launch_bounds__(256)
mixer(const float* __restrict__ q_agents,
      const int*   __restrict__ actions,
      const float* __restrict__ W_v2,
      const float* __restrict__ b_v2,
      float*       __restrict__ out)
{
    const int gw = (blockIdx.x * blockDim.x + threadIdx.x) >> 5;
    if (gw >= NS * 2) return;
    const int n    = gw >> 1;
    const int half = gw & 1;
    const int lane = threadIdx.x & 31;
    const int eg   = lane >> 2;         // 0..7 -> 8 e-values each
    const int slot = lane & 3;          // 0..3 action slot
    const int e0   = eg * 8;
    const unsigned FULL = 0xffffffffu;

    const float* Crow = g_C + (size_t)n * COLS;

    float qt_own = 0.f;
    if (lane < AG) {
        int a = actions[n * AG + lane];
        qt_own = q_agents[(size_t)(n * AG + lane) * ACT + a];
    }

    // v = relu(zv) @ W_v2 + b_v2
    float zv0 = Crow[1152 + lane];
    float zv1 = Crow[1184 + lane];
    float vp  = fmaxf(zv0, 0.f) * W_v2[lane] + fmaxf(zv1, 0.f) * W_v2[lane + 32];
    #pragma unroll
    for (int off = 16; off >= 1; off >>= 1)
        vp += __shfl_xor_sync(FULL, vp, off);
    const float v = vp + b_v2[0];

    // u2[e] = b1[e] + sum_j qt[j]*w1[j,e]   (fp32 accumulation)
    float u2[8];
    {
        float4 t0 = *(const float4*)(Crow + 1024 + e0);
        float4 t1 = *(const float4*)(Crow + 1024 + e0 + 4);
        u2[0]=t0.x; u2[1]=t0.y; u2[2]=t0.z; u2[3]=t0.w;
        u2[4]=t1.x; u2[5]=t1.y; u2[6]=t1.z; u2[7]=t1.w;
    }
    #pragma unroll 1
    for (int i = 0; i < AG; i++) {
        float qti = __shfl_sync(FULL, qt_own, i);
        float4 t0 = *(const float4*)(Crow + i * EDIM + e0);
        float4 t1 = *(const float4*)(Crow + i * EDIM + e0 + 4);
        u2[0] = fmaf(qti, t0.x, u2[0]); u2[1] = fmaf(qti, t0.y, u2[1]);
        u2[2] = fmaf(qti, t0.z, u2[2]); u2[3] = fmaf(qti, t0.w, u2[3]);
        u2[4] = fmaf(qti, t1.x, u2[4]); u2[5] = fmaf(qti, t1.y, u2[5]);
        u2[6] = fmaf(qti, t1.z, u2[6]); u2[7] = fmaf(qti, t1.w, u2[7]);
    }
    // pack u2 (log2-domain) into half2 pairs
    __half2 u2h[4];
    #pragma unroll
    for (int p = 0; p < 4; p++)
        u2h[p] = __floats2half2_rn(u2[2*p] * LOG2E, u2[2*p+1] * LOG2E);

    // wf slice: fp32 sum (exact -1 fold) + half2 pairs for the inner loop
    float swf = 0.f;
    __half2 wfh[4];
    {
        float4 t0 = *(const float4*)(Crow + 1088 + e0);
        float4 t1 = *(const float4*)(Crow + 1088 + e0 + 4);
        float wf[8];
        wf[0]=t0.x; wf[1]=t0.y; wf[2]=t0.z; wf[3]=t0.w;
        wf[4]=t1.x; wf[5]=t1.y; wf[6]=t1.z; wf[7]=t1.w;
        #pragma unroll
        for (int e = 0; e < 8; e++) swf += wf[e];
        #pragma unroll
        for (int p = 0; p < 4; p++) wfh[p] = __floats2half2_rn(wf[2*p], wf[2*p+1]);
    }

    const __half2 z2 = __float2half2_rn(0.f);

    const int i0 = half * 8;
    #pragma unroll 1
    for (int i = i0; i < i0 + 8; i++) {
        __half2 wh[4];
        {
            float4 t0 = *(const float4*)(Crow + i * EDIM + e0);
            float4 t1 = *(const float4*)(Crow + i * EDIM + e0 + 4);
            wh[0] = __floats2half2_rn(t0.x, t0.y);
            wh[1] = __floats2half2_rn(t0.z, t0.w);
            wh[2] = __floats2half2_rn(t1.x, t1.y);
            wh[3] = __floats2half2_rn(t1.z, t1.w);
        }
        float qti = __shfl_sync(FULL, qt_own, i);
        const float* qrow = q_agents + (size_t)(n * AG + i) * ACT;

        float qv[5];
        #pragma unroll
        for (int r = 0; r < 5; r++) qv[r] = qrow[r * 4 + slot];

        #pragma unroll
        for (int r = 0; r < 5; r++) {
            int act = r * 4 + slot;
            float deltaL = (qv[r] - qti) * LOG2E;
            __half2 dL2 = __float2half2_rn(deltaL);

            __half2 acc1h = z2, acc2h = z2;
            #pragma unroll
            for (int p = 0; p < 4; p++) {
                __half2 xh = __hfma2(dL2, wh[p], u2h[p]);
                acc1h = __hfma2(__hmax2(xh, z2), wfh[p], acc1h);
                acc2h = __hfma2(h2exp2(__hmin2(xh, z2)), wfh[p], acc2h);
            }
            float2 a1 = __half22float2(acc1h);
            float2 a2 = __half22float2(acc2h);
            float accv = fmaf(a1.x + a1.y, LN2, a2.x + a2.y) - swf;
            accv += __shfl_xor_sync(FULL, accv, 4);
            accv += __shfl_xor_sync(FULL, accv, 8);
            accv += __shfl_xor_sync(FULL, accv, 16);
            if (eg == 0)
                out[(size_t)n * MOUT + i * ACT + act] = accv + v;
        }
    }
}

// ============================================================================
extern "C" void kernel_launch(void* const* d_in, const int* in_sizes, int n_in,
                              void* d_out, int out_size) {
    const float* q_agents = (const float*)d_in[0];
    const int*   actions  = (const int*)d_in[1];
    const float* state    = (const float*)d_in[2];
    const float* W_h1 = (const float*)d_in[3];
    const float* b_h1 = (const float*)d_in[4];
    const float* W_b1 = (const float*)d_in[5];
    const float* b_b1 = (const float*)d_in[6];
    const float* W_hf = (const float*)d_in[7];
    const float* b_hf = (const float*)d_in[8];
    const float* W_v1 = (const float*)d_in[9];
    const float* b_v1 = (const float*)d_in[10];
    const float* W_v2 = (const float*)d_in[11];
    const float* b_v2 = (const float*)d_in[12];
    float* out = (float*)d_out;

    cudaFuncSetAttribute(gemm_tc, cudaFuncAttributeMaxDynamicSharedMemorySize, GEMM_SMEM);

    convert_split<<<CONV_GRID, 256>>>(
        W_h1, b_h1, W_b1, b_b1, W_hf, b_hf, W_v1, b_v1);

    dim3 g1(8, 32);
    gemm_tc<<<g1, 256, GEMM_SMEM>>>(state);

    mixer<<<(NS * 2 * 32 + 255) / 256, 256>>>(q_agents, actions, W_v2, b_v2, out);
    (void)in_sizes; (void)n_in; (void)out_size;
}

// round 15
// speedup vs baseline: 1.1263x; 1.1263x over previous
#include <cuda_runtime.h>
#include <cuda_bf16.h>
#include <cuda_fp16.h>
#include <cstdint>

// ---------------- problem constants ----------------
#define NS    4096      // B*T
#define SDIM  512
#define AG    16
#define ACT   20
#define MOUT  320
#define EDIM  64
#define COLS  1216      // 1024 w1 + 64 b1 + 64 wf + 64 zv
#define COLSP 1280      // padded to 8*160

#define LOG2E 1.4426950408889634f
#define LN2   0.6931471805599453f

// ---------------- device scratch ----------------
__device__ float   g_C[NS * COLS];
__device__ __half  g_A0[NS * SDIM];          // fp16(state)
__device__ __half  g_B0[COLSP * SDIM];       // fp16(W)
__device__ float   g_bias[COLSP];

// ---------------- PTX helpers (sm_100-safe) ----------------
__device__ __forceinline__ uint32_t smem_u32(const void* p) {
    uint32_t a;
    asm("{ .reg .u64 t; cvta.to.shared.u64 t, %1; cvt.u32.u64 %0, t; }" : "=r"(a) : "l"(p));
    return a;
}
__device__ __forceinline__ void cp16(uint32_t dst, const void* src) {
    asm volatile("cp.async.cg.shared.global [%0], [%1], 16;" :: "r"(dst), "l"(src));
}
#define CP_COMMIT() asm volatile("cp.async.commit_group;" ::: "memory")
#define CP_WAIT2()  asm volatile("cp.async.wait_group 2;" ::: "memory")

__device__ __forceinline__ void ldm_x4(uint32_t* r, uint32_t addr) {
    asm volatile("ldmatrix.sync.aligned.m8n8.x4.shared.b16 {%0,%1,%2,%3}, [%4];"
        : "=r"(r[0]), "=r"(r[1]), "=r"(r[2]), "=r"(r[3]) : "r"(addr));
}
__device__ __forceinline__ void ldm_x2(uint32_t* r, uint32_t addr) {
    asm volatile("ldmatrix.sync.aligned.m8n8.x2.shared.b16 {%0,%1}, [%2];"
        : "=r"(r[0]), "=r"(r[1]) : "r"(addr));
}
__device__ __forceinline__ void mma_f16(float* c, const uint32_t* a, uint32_t b0, uint32_t b1) {
    asm volatile(
        "mma.sync.aligned.m16n8k16.row.col.f32.f16.f16.f32 "
        "{%0,%1,%2,%3}, {%4,%5,%6,%7}, {%8,%9}, {%0,%1,%2,%3};"
        : "+f"(c[0]), "+f"(c[1]), "+f"(c[2]), "+f"(c[3])
        : "r"(a[0]), "r"(a[1]), "r"(a[2]), "r"(a[3]), "r"(b0), "r"(b1));
}

// ============================================================================
// Kernel 0: A -> fp16; W -> fp16; concat bias. (R8/R12-proven grid shape)
// ============================================================================
__device__ __forceinline__ uint32_t pack2h(float a, float b) {
    __half2 t(__float2half_rn(a), __float2half_rn(b));
    return *(uint32_t*)&t;
}

#define CONV_ABLK 512
#define CONV_BBLK 160
#define CONV_GRID (CONV_ABLK + CONV_BBLK + 5)

__global__ void __launch_bounds__(256)
convert_split(const float* __restrict__ state,
              const float* __restrict__ W_h1, const float* __restrict__ b_h1,
              const float* __restrict__ W_b1, const float* __restrict__ b_b1,
              const float* __restrict__ W_hf, const float* __restrict__ b_hf,
              const float* __restrict__ W_v1, const float* __restrict__ b_v1)
{
    const int blk = blockIdx.x;
    const int tid = threadIdx.x;

    if (blk < CONV_ABLK) {
        int base = blk * 1024 + tid;
        float4 v[4];
        #pragma unroll
        for (int k = 0; k < 4; k++)
            v[k] = ((const float4*)state)[base + k * 256];
        #pragma unroll
        for (int k = 0; k < 4; k++) {
            uint2 p;
            p.x = pack2h(v[k].x, v[k].y);  p.y = pack2h(v[k].z, v[k].w);
            ((uint2*)g_A0)[base + k * 256] = p;
        }
    } else if (blk < CONV_ABLK + CONV_BBLK) {
        int base = (blk - CONV_ABLK) * 1024 + tid;
        float4 v[4];
        #pragma unroll
        for (int k = 0; k < 4; k++) {
            int q = base + k * 256;
            int row = q >> 7;            // 128 quads per 512-wide row
            int cq  = q & 127;
            if (row < 1024)      v[k] = ((const float4*)(W_h1 + (size_t)row * SDIM))[cq];
            else if (row < 1088) v[k] = ((const float4*)(W_b1 + (size_t)(row - 1024) * SDIM))[cq];
            else if (row < 1152) v[k] = ((const float4*)(W_hf + (size_t)(row - 1088) * SDIM))[cq];
            else if (row < 1216) v[k] = ((const float4*)(W_v1 + (size_t)(row - 1152) * SDIM))[cq];
            else                 v[k] = make_float4(0.f, 0.f, 0.f, 0.f);
        }
        #pragma unroll
        for (int k = 0; k < 4; k++) {
            uint2 p;
            p.x = pack2h(v[k].x, v[k].y);  p.y = pack2h(v[k].z, v[k].w);
            ((uint2*)g_B0)[base + k * 256] = p;
        }
    } else {
        int c = (blk - CONV_ABLK - CONV_BBLK) * 256 + tid;
        if (c < COLSP) {
            float b = 0.f;
            if (c < 1024)      b = b_h1[c];
            else if (c < 1088) b = b_b1[c - 1024];
            else if (c < 1152) b = b_hf[c - 1088];
            else if (c < 1216) b = b_v1[c - 1152];
            g_bias[c] = b;
        }
    }
}

// ============================================================================
// Kernel 1: HMMA fp16 GEMM: C = A0*B0 + bias  (identical to R8/R12)
// Tile 128(M) x 160(N) x 32(K). grid (8, 32) = 256 CTAs, 2 CTAs/SM.
// 4-stage cp.async, lookahead 2, single barrier per k-iter (R8 proof).
// ============================================================================
#define ROWB   80
#define MATBA  (128 * ROWB)             // 10240 B
#define MATBB  (160 * ROWB)             // 12800 B
#define STAGEB (MATBA + MATBB)          // 23040 B
#define NSTAGE 4
#define GEMM_SMEM (NSTAGE * STAGEB)     // 92160 B
#define NCHUNKS ((128 + 160) * 4)       // 1152 16B-chunks per stage

__device__ __forceinline__ void load_stage(uint32_t sb, int tid, int rowA, int rowB, int kt) {
    #pragma unroll
    for (int t = 0; t < 5; t++) {
        int id = tid + t * 256;          // 0..1279
        if (id < NCHUNKS) {
            if (id < 512) {
                int r = id >> 2, c = id & 3;
                cp16(sb + (uint32_t)(r * ROWB + c * 16),
                     (const char*)g_A0 + ((size_t)(rowA + r) * SDIM + kt) * 2 + c * 16);
            } else {
                int q = id - 512;
                int r = q >> 2, c = q & 3;
                cp16(sb + MATBA + (uint32_t)(r * ROWB + c * 16),
                     (const char*)g_B0 + ((size_t)(rowB + r) * SDIM + kt) * 2 + c * 16);
            }
        }
    }
}

__global__ void __launch_bounds__(256, 2)
gemm_tc()
{
    extern __shared__ char smem[];
    const uint32_t sbase = smem_u32(smem);
    const int tid  = threadIdx.x;
    const int wid  = tid >> 5;
    const int lane = tid & 31;
    const int cb   = blockIdx.x;   // 0..7
    const int rb   = blockIdx.y;   // 0..31

    const int warp_m = wid >> 2;
    const int warp_n = wid & 3;
    const int rowA = rb * 128;
    const int rowB = cb * 160;

    float c[4][5][4];
    #pragma unroll
    for (int i = 0; i < 4; i++)
        #pragma unroll
        for (int j = 0; j < 5; j++)
            #pragma unroll
            for (int q = 0; q < 4; q++)
                c[i][j][q] = 0.f;

    load_stage(sbase + 0 * STAGEB, tid, rowA, rowB, 0);
    CP_COMMIT();
    load_stage(sbase + 1 * STAGEB, tid, rowA, rowB, 32);
    CP_COMMIT();

    const uint32_t lrow  = (uint32_t)(lane & 15) * ROWB;
    const uint32_t lcol  = (uint32_t)(lane >> 4) * 16;
    const uint32_t lrow2 = (uint32_t)(lane & 7) * ROWB;
    const uint32_t lcol2 = (uint32_t)((lane >> 3) & 1) * 16;

    const int NK = SDIM / 32;   // 16
    for (int kt = 0; kt < NK; kt++) {
        if (kt + 2 < NK)
            load_stage(sbase + ((kt + 2) % NSTAGE) * STAGEB, tid, rowA, rowB, (kt + 2) * 32);
        CP_COMMIT();
        CP_WAIT2();
        __syncthreads();

        const uint32_t st = sbase + (kt % NSTAGE) * STAGEB;
        const uint32_t aAddr   = st + lrow + lcol;
        const uint32_t bBase   = st + MATBA + (uint32_t)(warp_n * 40) * ROWB;
        const uint32_t bAddrX4 = bBase + lrow + lcol;
        const uint32_t bAddrX2 = bBase + 32 * ROWB + lrow2 + lcol2;

        #pragma unroll
        for (int kk = 0; kk < 2; kk++) {
            uint32_t a[4][4];
            #pragma unroll
            for (int mt = 0; mt < 4; mt++)
                ldm_x4(a[mt], aAddr + (uint32_t)((warp_m * 64 + mt * 16) * ROWB + kk * 32));

            uint32_t b4a[4], b4b[4], b2[2];
            ldm_x4(b4a, bAddrX4 + (uint32_t)(kk * 32));
            ldm_x4(b4b, bAddrX4 + (uint32_t)(16 * ROWB + kk * 32));
            ldm_x2(b2,  bAddrX2 + (uint32_t)(kk * 32));

            #pragma unroll
            for (int mt = 0; mt < 4; mt++) {
                mma_f16(c[mt][0], a[mt], b4a[0], b4a[2]);
                mma_f16(c[mt][1], a[mt], b4a[1], b4a[3]);
                mma_f16(c[mt][2], a[mt], b4b[0], b4b[2]);
                mma_f16(c[mt][3], a[mt], b4b[1], b4b[3]);
                mma_f16(c[mt][4], a[mt], b2[0],  b2[1]);
            }
        }
        // no trailing barrier (stage reuse distance 3 mod 4; see R8)
    }

    // epilogue
    const int rbase = rb * 128 + warp_m * 64 + (lane >> 2);
    const int cbase = cb * 160 + warp_n * 40 + (lane & 3) * 2;
    #pragma unroll
    for (int nt = 0; nt < 5; nt++) {
        int col = cbase + nt * 8;
        if (col >= COLS) continue;
        float2 bias = *(const float2*)(g_bias + col);
        #pragma unroll
        for (int mt = 0; mt < 4; mt++) {
            int r0 = rbase + mt * 16;
            float2 v0, v1;
            v0.x = c[mt][nt][0] + bias.x; v0.y = c[mt][nt][1] + bias.y;
            v1.x = c[mt][nt][2] + bias.x; v1.y = c[mt][nt][3] + bias.y;
            *(float2*)(g_C + (size_t)r0 * COLS + col)       = v0;
            *(float2*)(g_C + (size_t)(r0 + 8) * COLS + col) = v1;
        }
    }
}

// ============================================================================
// Kernel 2: mixer v6. TWO warps per sample (agents split 8/8), packed-half2
// inner loop (R12). NEW: agent loops unrolled x2 -> 4 independent float4 LDGs
// per unrolled iteration (double MLP on the dependent g_C chain). Per-lane
// fp32 accumulation order unchanged -> bit-identical results to R12.
// ============================================================================
__global__ void __launch_bounds__(256)
mixer(const float* __restrict__ q_agents,
      const int*   __restrict__ actions,
      const float* __restrict__ W_v2,
      const float* __restrict__ b_v2,
      float*       __restrict__ out)
{
    const int gw = (blockIdx.x * blockDim.x + threadIdx.x) >> 5;
    if (gw >= NS * 2) return;
    const int n    = gw >> 1;
    const int half = gw & 1;
    const int lane = threadIdx.x & 31;
    const int eg   = lane >> 2;         // 0..7 -> 8 e-values each
    const int slot = lane & 3;          // 0..3 action slot
    const int e0   = eg * 8;
    const unsigned FULL = 0xffffffffu;

    const float* Crow = g_C + (size_t)n * COLS;

    float qt_own = 0.f;
    if (lane < AG) {
        int a = actions[n * AG + lane];
        qt_own = q_agents[(size_t)(n * AG + lane) * ACT + a];
    }

    // v = relu(zv) @ W_v2 + b_v2
    float zv0 = Crow[1152 + lane];
    float zv1 = Crow[1184 + lane];
    float vp  = fmaxf(zv0, 0.f) * W_v2[lane] + fmaxf(zv1, 0.f) * W_v2[lane + 32];
    #pragma unroll
    for (int off = 16; off >= 1; off >>= 1)
        vp += __shfl_xor_sync(FULL, vp, off);
    const float v = vp + b_v2[0];

    // u2[e] = b1[e] + sum_j qt[j]*w1[j,e]   (fp32, unroll 2 for MLP)
    float u2[8];
    {
        float4 t0 = *(const float4*)(Crow + 1024 + e0);
        float4 t1 = *(const float4*)(Crow + 1024 + e0 + 4);
        u2[0]=t0.x; u2[1]=t0.y; u2[2]=t0.z; u2[3]=t0.w;
        u2[4]=t1.x; u2[5]=t1.y; u2[6]=t1.z; u2[7]=t1.w;
    }
    #pragma unroll 2
    for (int i = 0; i < AG; i++) {
        float qti = __shfl_sync(FULL, qt_own, i);
        float4 t0 = *(const float4*)(Crow + i * EDIM + e0);
        float4 t1 = *(const float4*)(Crow + i * EDIM + e0 + 4);
        u2[0] = fmaf(qti, t0.x, u2[0]); u2[1] = fmaf(qti, t0.y, u2[1]);
        u2[2] = fmaf(qti, t0.z, u2[2]); u2[3] = fmaf(qti, t0.w, u2[3]);
        u2[4] = fmaf(qti, t1.x, u2[4]); u2[5] = fmaf(qti, t1.y, u2[5]);
        u2[6] = fmaf(qti, t1.z, u2[6]); u2[7] = fmaf(qti, t1.w, u2[7]);
    }
    // pack u2 (log2-domain) into half2 pairs
    __half2 u2h[4];
    #pragma unroll
    for (int p = 0; p < 4; p++)
        u2h[p] = __floats2half2_rn(u2[2*p] * LOG2E, u2[2*p+1] * LOG2E);

    // wf slice: fp32 sum (exact -1 fold) + half2 pairs for the inner loop
    float swf = 0.f;
    __half2 wfh[4];
    {
        float4 t0 = *(const float4*)(Crow + 1088 + e0);
        float4 t1 = *(const float4*)(Crow + 1088 + e0 + 4);
        float wf[8];
        wf[0]=t0.x; wf[1]=t0.y; wf[2]=t0.z; wf[3]=t0.w;
        wf[4]=t1.x; wf[5]=t1.y; wf[6]=t1.z; wf[7]=t1.w;
        #pragma unroll
        for (int e = 0; e < 8; e++) swf += wf[e];
        #pragma unroll
        for (int p = 0; p < 4; p++) wfh[p] = __floats2half2_rn(wf[2*p], wf[2*p+1]);
    }

    const __half2 z2 = __float2half2_rn(0.f);

    const int i0 = half * 8;
    #pragma unroll 2
    for (int i = i0; i < i0 + 8; i++) {
        __half2 wh[4];
        {
            float4 t0 = *(const float4*)(Crow + i * EDIM + e0);
            float4 t1 = *(const float4*)(Crow + i * EDIM + e0 + 4);
            wh[0] = __floats2half2_rn(t0.x, t0.y);
            wh[1] = __floats2half2_rn(t0.z, t0.w);
            wh[2] = __floats2half2_rn(t1.x, t1.y);
            wh[3] = __floats2half2_rn(t1.z, t1.w);
        }
        float qti = __shfl_sync(FULL, qt_own, i);
        const float* qrow = q_agents + (size_t)(n * AG + i) * ACT;

        float qv[5];
        #pragma unroll
        for (int r = 0; r < 5; r++) qv[r] = qrow[r * 4 + slot];

        #pragma unroll
        for (int r = 0; r < 5; r++) {
            int act = r * 4 + slot;
            float deltaL = (qv[r] - qti) * LOG2E;
            __half2 dL2 = __float2half2_rn(deltaL);

            __half2 acc1h = z2, acc2h = z2;
            #pragma unroll
            for (int p = 0; p < 4; p++) {
                __half2 xh = __hfma2(dL2, wh[p], u2h[p]);
                acc1h = __hfma2(__hmax2(xh, z2), wfh[p], acc1h);
                acc2h = __hfma2(h2exp2(__hmin2(xh, z2)), wfh[p], acc2h);
            }
            float2 a1 = __half22float2(acc1h);
            float2 a2 = __half22float2(acc2h);
            float accv = fmaf(a1.x + a1.y, LN2, a2.x + a2.y) - swf;
            accv += __shfl_xor_sync(FULL, accv, 4);
            accv += __shfl_xor_sync(FULL, accv, 8);
            accv += __shfl_xor_sync(FULL, accv, 16);
            if (eg == 0)
                out[(size_t)n * MOUT + i * ACT + act] = accv + v;
        }
    }
}

// ============================================================================
extern "C" void kernel_launch(void* const* d_in, const int* in_sizes, int n_in,
                              void* d_out, int out_size) {
    const float* q_agents = (const float*)d_in[0];
    const int*   actions  = (const int*)d_in[1];
    const float* state    = (const float*)d_in[2];
    const float* W_h1 = (const float*)d_in[3];
    const float* b_h1 = (const float*)d_in[4];
    const float* W_b1 = (const float*)d_in[5];
    const float* b_b1 = (const float*)d_in[6];
    const float* W_hf = (const float*)d_in[7];
    const float* b_hf = (const float*)d_in[8];
    const float* W_v1 = (const float*)d_in[9];
    const float* b_v1 = (const float*)d_in[10];
    const float* W_v2 = (const float*)d_in[11];
    const float* b_v2 = (const float*)d_in[12];
    float* out = (float*)d_out;

    cudaFuncSetAttribute(gemm_tc, cudaFuncAttributeMaxDynamicSharedMemorySize, GEMM_SMEM);

    convert_split<<<CONV_GRID, 256>>>(
        state, W_h1, b_h1, W_b1, b_b1, W_hf, b_hf, W_v1, b_v1);

    dim3 g1(8, 32);
    gemm_tc<<<g1, 256, GEMM_SMEM>>>();

    mixer<<<(NS * 2 * 32 + 255) / 256, 256>>>(q_agents, actions, W_v2, b_v2, out);
    (void)in_sizes; (void)n_in; (void)out_size;
}

// round 16
// speedup vs baseline: 1.1274x; 1.0010x over previous
#include <cuda_runtime.h>
#include <cuda_bf16.h>
#include <cuda_fp16.h>
#include <cstdint>

// ---------------- problem constants ----------------
#define NS    4096      // B*T
#define SDIM  512
#define AG    16
#define ACT   20
#define MOUT  320
#define EDIM  64
#define COLS  1216      // 1024 w1 + 64 b1 + 64 wf + 64 zv
#define COLSP 1280      // padded to 8*160

#define LOG2E 1.4426950408889634f
#define LN2   0.6931471805599453f

// ---------------- device scratch ----------------
__device__ float   g_C[NS * COLS];
__device__ __half  g_A0[NS * SDIM];          // fp16(state)
__device__ __half  g_B0[COLSP * SDIM];       // fp16(W)
__device__ float   g_bias[COLSP];

// ---------------- PTX helpers (sm_100-safe) ----------------
__device__ __forceinline__ uint32_t smem_u32(const void* p) {
    uint32_t a;
    asm("{ .reg .u64 t; cvta.to.shared.u64 t, %1; cvt.u32.u64 %0, t; }" : "=r"(a) : "l"(p));
    return a;
}
__device__ __forceinline__ void cp16(uint32_t dst, const void* src) {
    asm volatile("cp.async.cg.shared.global [%0], [%1], 16;" :: "r"(dst), "l"(src));
}
#define CP_COMMIT() asm volatile("cp.async.commit_group;" ::: "memory")
#define CP_WAIT2()  asm volatile("cp.async.wait_group 2;" ::: "memory")

__device__ __forceinline__ void ldm_x4(uint32_t* r, uint32_t addr) {
    asm volatile("ldmatrix.sync.aligned.m8n8.x4.shared.b16 {%0,%1,%2,%3}, [%4];"
        : "=r"(r[0]), "=r"(r[1]), "=r"(r[2]), "=r"(r[3]) : "r"(addr));
}
__device__ __forceinline__ void ldm_x2(uint32_t* r, uint32_t addr) {
    asm volatile("ldmatrix.sync.aligned.m8n8.x2.shared.b16 {%0,%1}, [%2];"
        : "=r"(r[0]), "=r"(r[1]) : "r"(addr));
}
__device__ __forceinline__ void mma_f16(float* c, const uint32_t* a, uint32_t b0, uint32_t b1) {
    asm volatile(
        "mma.sync.aligned.m16n8k16.row.col.f32.f16.f16.f32 "
        "{%0,%1,%2,%3}, {%4,%5,%6,%7}, {%8,%9}, {%0,%1,%2,%3};"
        : "+f"(c[0]), "+f"(c[1]), "+f"(c[2]), "+f"(c[3])
        : "r"(a[0]), "r"(a[1]), "r"(a[2]), "r"(a[3]), "r"(b0), "r"(b1));
}

// ============================================================================
// Kernel 0: A -> fp16; W -> fp16; concat bias. (R8/R12-proven grid shape)
// ============================================================================
__device__ __forceinline__ uint32_t pack2h(float a, float b) {
    __half2 t(__float2half_rn(a), __float2half_rn(b));
    return *(uint32_t*)&t;
}

#define CONV_ABLK 512
#define CONV_BBLK 160
#define CONV_GRID (CONV_ABLK + CONV_BBLK + 5)

__global__ void __launch_bounds__(256)
convert_split(const float* __restrict__ state,
              const float* __restrict__ W_h1, const float* __restrict__ b_h1,
              const float* __restrict__ W_b1, const float* __restrict__ b_b1,
              const float* __restrict__ W_hf, const float* __restrict__ b_hf,
              const float* __restrict__ W_v1, const float* __restrict__ b_v1)
{
    const int blk = blockIdx.x;
    const int tid = threadIdx.x;

    if (blk < CONV_ABLK) {
        int base = blk * 1024 + tid;
        float4 v[4];
        #pragma unroll
        for (int k = 0; k < 4; k++)
            v[k] = ((const float4*)state)[base + k * 256];
        #pragma unroll
        for (int k = 0; k < 4; k++) {
            uint2 p;
            p.x = pack2h(v[k].x, v[k].y);  p.y = pack2h(v[k].z, v[k].w);
            ((uint2*)g_A0)[base + k * 256] = p;
        }
    } else if (blk < CONV_ABLK + CONV_BBLK) {
        int base = (blk - CONV_ABLK) * 1024 + tid;
        float4 v[4];
        #pragma unroll
        for (int k = 0; k < 4; k++) {
            int q = base + k * 256;
            int row = q >> 7;            // 128 quads per 512-wide row
            int cq  = q & 127;
            if (row < 1024)      v[k] = ((const float4*)(W_h1 + (size_t)row * SDIM))[cq];
            else if (row < 1088) v[k] = ((const float4*)(W_b1 + (size_t)(row - 1024) * SDIM))[cq];
            else if (row < 1152) v[k] = ((const float4*)(W_hf + (size_t)(row - 1088) * SDIM))[cq];
            else if (row < 1216) v[k] = ((const float4*)(W_v1 + (size_t)(row - 1152) * SDIM))[cq];
            else                 v[k] = make_float4(0.f, 0.f, 0.f, 0.f);
        }
        #pragma unroll
        for (int k = 0; k < 4; k++) {
            uint2 p;
            p.x = pack2h(v[k].x, v[k].y);  p.y = pack2h(v[k].z, v[k].w);
            ((uint2*)g_B0)[base + k * 256] = p;
        }
    } else {
        int c = (blk - CONV_ABLK - CONV_BBLK) * 256 + tid;
        if (c < COLSP) {
            float b = 0.f;
            if (c < 1024)      b = b_h1[c];
            else if (c < 1088) b = b_b1[c - 1024];
            else if (c < 1152) b = b_hf[c - 1088];
            else if (c < 1216) b = b_v1[c - 1152];
            g_bias[c] = b;
        }
    }
}

// ============================================================================
// Kernel 1: HMMA fp16 GEMM: C = A0*B0 + bias  (identical to R8/R12)
// Tile 128(M) x 160(N) x 32(K). grid (8, 32) = 256 CTAs, 2 CTAs/SM.
// 4-stage cp.async, lookahead 2, single barrier per k-iter (R8 proof).
// ============================================================================
#define ROWB   80
#define MATBA  (128 * ROWB)             // 10240 B
#define MATBB  (160 * ROWB)             // 12800 B
#define STAGEB (MATBA + MATBB)          // 23040 B
#define NSTAGE 4
#define GEMM_SMEM (NSTAGE * STAGEB)     // 92160 B
#define NCHUNKS ((128 + 160) * 4)       // 1152 16B-chunks per stage

__device__ __forceinline__ void load_stage(uint32_t sb, int tid, int rowA, int rowB, int kt) {
    #pragma unroll
    for (int t = 0; t < 5; t++) {
        int id = tid + t * 256;          // 0..1279
        if (id < NCHUNKS) {
            if (id < 512) {
                int r = id >> 2, c = id & 3;
                cp16(sb + (uint32_t)(r * ROWB + c * 16),
                     (const char*)g_A0 + ((size_t)(rowA + r) * SDIM + kt) * 2 + c * 16);
            } else {
                int q = id - 512;
                int r = q >> 2, c = q & 3;
                cp16(sb + MATBA + (uint32_t)(r * ROWB + c * 16),
                     (const char*)g_B0 + ((size_t)(rowB + r) * SDIM + kt) * 2 + c * 16);
            }
        }
    }
}

__global__ void __launch_bounds__(256, 2)
gemm_tc()
{
    extern __shared__ char smem[];
    const uint32_t sbase = smem_u32(smem);
    const int tid  = threadIdx.x;
    const int wid  = tid >> 5;
    const int lane = tid & 31;
    const int cb   = blockIdx.x;   // 0..7
    const int rb   = blockIdx.y;   // 0..31

    const int warp_m = wid >> 2;
    const int warp_n = wid & 3;
    const int rowA = rb * 128;
    const int rowB = cb * 160;

    float c[4][5][4];
    #pragma unroll
    for (int i = 0; i < 4; i++)
        #pragma unroll
        for (int j = 0; j < 5; j++)
            #pragma unroll
            for (int q = 0; q < 4; q++)
                c[i][j][q] = 0.f;

    load_stage(sbase + 0 * STAGEB, tid, rowA, rowB, 0);
    CP_COMMIT();
    load_stage(sbase + 1 * STAGEB, tid, rowA, rowB, 32);
    CP_COMMIT();

    const uint32_t lrow  = (uint32_t)(lane & 15) * ROWB;
    const uint32_t lcol  = (uint32_t)(lane >> 4) * 16;
    const uint32_t lrow2 = (uint32_t)(lane & 7) * ROWB;
    const uint32_t lcol2 = (uint32_t)((lane >> 3) & 1) * 16;

    const int NK = SDIM / 32;   // 16
    for (int kt = 0; kt < NK; kt++) {
        if (kt + 2 < NK)
            load_stage(sbase + ((kt + 2) % NSTAGE) * STAGEB, tid, rowA, rowB, (kt + 2) * 32);
        CP_COMMIT();
        CP_WAIT2();
        __syncthreads();

        const uint32_t st = sbase + (kt % NSTAGE) * STAGEB;
        const uint32_t aAddr   = st + lrow + lcol;
        const uint32_t bBase   = st + MATBA + (uint32_t)(warp_n * 40) * ROWB;
        const uint32_t bAddrX4 = bBase + lrow + lcol;
        const uint32_t bAddrX2 = bBase + 32 * ROWB + lrow2 + lcol2;

        #pragma unroll
        for (int kk = 0; kk < 2; kk++) {
            uint32_t a[4][4];
            #pragma unroll
            for (int mt = 0; mt < 4; mt++)
                ldm_x4(a[mt], aAddr + (uint32_t)((warp_m * 64 + mt * 16) * ROWB + kk * 32));

            uint32_t b4a[4], b4b[4], b2[2];
            ldm_x4(b4a, bAddrX4 + (uint32_t)(kk * 32));
            ldm_x4(b4b, bAddrX4 + (uint32_t)(16 * ROWB + kk * 32));
            ldm_x2(b2,  bAddrX2 + (uint32_t)(kk * 32));

            #pragma unroll
            for (int mt = 0; mt < 4; mt++) {
                mma_f16(c[mt][0], a[mt], b4a[0], b4a[2]);
                mma_f16(c[mt][1], a[mt], b4a[1], b4a[3]);
                mma_f16(c[mt][2], a[mt], b4b[0], b4b[2]);
                mma_f16(c[mt][3], a[mt], b4b[1], b4b[3]);
                mma_f16(c[mt][4], a[mt], b2[0],  b2[1]);
            }
        }
        // no trailing barrier (stage reuse distance 3 mod 4; see R8)
    }

    // epilogue
    const int rbase = rb * 128 + warp_m * 64 + (lane >> 2);
    const int cbase = cb * 160 + warp_n * 40 + (lane & 3) * 2;
    #pragma unroll
    for (int nt = 0; nt < 5; nt++) {
        int col = cbase + nt * 8;
        if (col >= COLS) continue;
        float2 bias = *(const float2*)(g_bias + col);
        #pragma unroll
        for (int mt = 0; mt < 4; mt++) {
            int r0 = rbase + mt * 16;
            float2 v0, v1;
            v0.x = c[mt][nt][0] + bias.x; v0.y = c[mt][nt][1] + bias.y;
            v1.x = c[mt][nt][2] + bias.x; v1.y = c[mt][nt][3] + bias.y;
            *(float2*)(g_C + (size_t)r0 * COLS + col)       = v0;
            *(float2*)(g_C + (size_t)(r0 + 8) * COLS + col) = v1;
        }
    }
}

// ============================================================================
// Kernel 2: mixer v6. TWO warps per sample (agents split 8/8), packed-half2
// inner loop (R12). NEW: agent loops unrolled x2 -> 4 independent float4 LDGs
// per unrolled iteration (double MLP on the dependent g_C chain). Per-lane
// fp32 accumulation order unchanged -> bit-identical results to R12.
// ============================================================================
__global__ void __launch_bounds__(256)
mixer(const float* __restrict__ q_agents,
      const int*   __restrict__ actions,
      const float* __restrict__ W_v2,
      const float* __restrict__ b_v2,
      float*       __restrict__ out)
{
    const int gw = (blockIdx.x * blockDim.x + threadIdx.x) >> 5;
    if (gw >= NS * 2) return;
    const int n    = gw >> 1;
    const int half = gw & 1;
    const int lane = threadIdx.x & 31;
    const int eg   = lane >> 2;         // 0..7 -> 8 e-values each
    const int slot = lane & 3;          // 0..3 action slot
    const int e0   = eg * 8;
    const unsigned FULL = 0xffffffffu;

    const float* Crow = g_C + (size_t)n * COLS;

    float qt_own = 0.f;
    if (lane < AG) {
        int a = actions[n * AG + lane];
        qt_own = q_agents[(size_t)(n * AG + lane) * ACT + a];
    }

    // v = relu(zv) @ W_v2 + b_v2
    float zv0 = Crow[1152 + lane];
    float zv1 = Crow[1184 + lane];
    float vp  = fmaxf(zv0, 0.f) * W_v2[lane] + fmaxf(zv1, 0.f) * W_v2[lane + 32];
    #pragma unroll
    for (int off = 16; off >= 1; off >>= 1)
        vp += __shfl_xor_sync(FULL, vp, off);
    const float v = vp + b_v2[0];

    // u2[e] = b1[e] + sum_j qt[j]*w1[j,e]   (fp32, unroll 2 for MLP)
    float u2[8];
    {
        float4 t0 = *(const float4*)(Crow + 1024 + e0);
        float4 t1 = *(const float4*)(Crow + 1024 + e0 + 4);
        u2[0]=t0.x; u2[1]=t0.y; u2[2]=t0.z; u2[3]=t0.w;
        u2[4]=t1.x; u2[5]=t1.y; u2[6]=t1.z; u2[7]=t1.w;
    }
    #pragma unroll 2
    for (int i = 0; i < AG; i++) {
        float qti = __shfl_sync(FULL, qt_own, i);
        float4 t0 = *(const float4*)(Crow + i * EDIM + e0);
        float4 t1 = *(const float4*)(Crow + i * EDIM + e0 + 4);
        u2[0] = fmaf(qti, t0.x, u2[0]); u2[1] = fmaf(qti, t0.y, u2[1]);
        u2[2] = fmaf(qti, t0.z, u2[2]); u2[3] = fmaf(qti, t0.w, u2[3]);
        u2[4] = fmaf(qti, t1.x, u2[4]); u2[5] = fmaf(qti, t1.y, u2[5]);
        u2[6] = fmaf(qti, t1.z, u2[6]); u2[7] = fmaf(qti, t1.w, u2[7]);
    }
    // pack u2 (log2-domain) into half2 pairs
    __half2 u2h[4];
    #pragma unroll
    for (int p = 0; p < 4; p++)
        u2h[p] = __floats2half2_rn(u2[2*p] * LOG2E, u2[2*p+1] * LOG2E);

    // wf slice: fp32 sum (exact -1 fold) + half2 pairs for the inner loop
    float swf = 0.f;
    __half2 wfh[4];
    {
        float4 t0 = *(const float4*)(Crow + 1088 + e0);
        float4 t1 = *(const float4*)(Crow + 1088 + e0 + 4);
        float wf[8];
        wf[0]=t0.x; wf[1]=t0.y; wf[2]=t0.z; wf[3]=t0.w;
        wf[4]=t1.x; wf[5]=t1.y; wf[6]=t1.z; wf[7]=t1.w;
        #pragma unroll
        for (int e = 0; e < 8; e++) swf += wf[e];
        #pragma unroll
        for (int p = 0; p < 4; p++) wfh[p] = __floats2half2_rn(wf[2*p], wf[2*p+1]);
    }

    const __half2 z2 = __float2half2_rn(0.f);

    const int i0 = half * 8;
    #pragma unroll 2
    for (int i = i0; i < i0 + 8; i++) {
        __half2 wh[4];
        {
            float4 t0 = *(const float4*)(Crow + i * EDIM + e0);
            float4 t1 = *(const float4*)(Crow + i * EDIM + e0 + 4);
            wh[0] = __floats2half2_rn(t0.x, t0.y);
            wh[1] = __floats2half2_rn(t0.z, t0.w);
            wh[2] = __floats2half2_rn(t1.x, t1.y);
            wh[3] = __floats2half2_rn(t1.z, t1.w);
        }
        float qti = __shfl_sync(FULL, qt_own, i);
        const float* qrow = q_agents + (size_t)(n * AG + i) * ACT;

        float qv[5];
        #pragma unroll
        for (int r = 0; r < 5; r++) qv[r] = qrow[r * 4 + slot];

        #pragma unroll
        for (int r = 0; r < 5; r++) {
            int act = r * 4 + slot;
            float deltaL = (qv[r] - qti) * LOG2E;
            __half2 dL2 = __float2half2_rn(deltaL);

            __half2 acc1h = z2, acc2h = z2;
            #pragma unroll
            for (int p = 0; p < 4; p++) {
                __half2 xh = __hfma2(dL2, wh[p], u2h[p]);
                acc1h = __hfma2(__hmax2(xh, z2), wfh[p], acc1h);
                acc2h = __hfma2(h2exp2(__hmin2(xh, z2)), wfh[p], acc2h);
            }
            float2 a1 = __half22float2(acc1h);
            float2 a2 = __half22float2(acc2h);
            float accv = fmaf(a1.x + a1.y, LN2, a2.x + a2.y) - swf;
            accv += __shfl_xor_sync(FULL, accv, 4);
            accv += __shfl_xor_sync(FULL, accv, 8);
            accv += __shfl_xor_sync(FULL, accv, 16);
            if (eg == 0)
                out[(size_t)n * MOUT + i * ACT + act] = accv + v;
        }
    }
}

// ============================================================================
extern "C" void kernel_launch(void* const* d_in, const int* in_sizes, int n_in,
                              void* d_out, int out_size) {
    const float* q_agents = (const float*)d_in[0];
    const int*   actions  = (const int*)d_in[1];
    const float* state    = (const float*)d_in[2];
    const float* W_h1 = (const float*)d_in[3];
    const float* b_h1 = (const float*)d_in[4];
    const float* W_b1 = (const float*)d_in[5];
    const float* b_b1 = (const float*)d_in[6];
    const float* W_hf = (const float*)d_in[7];
    const float* b_hf = (const float*)d_in[8];
    const float* W_v1 = (const float*)d_in[9];
    const float* b_v1 = (const float*)d_in[10];
    const float* W_v2 = (const float*)d_in[11];
    const float* b_v2 = (const float*)d_in[12];
    float* out = (float*)d_out;

    cudaFuncSetAttribute(gemm_tc, cudaFuncAttributeMaxDynamicSharedMemorySize, GEMM_SMEM);

    convert_split<<<CONV_GRID, 256>>>(
        state, W_h1, b_h1, W_b1, b_b1, W_hf, b_hf, W_v1, b_v1);

    dim3 g1(8, 32);
    gemm_tc<<<g1, 256, GEMM_SMEM>>>();

    mixer<<<(NS * 2 * 32 + 255) / 256, 256>>>(q_agents, actions, W_v2, b_v2, out);
    (void)in_sizes; (void)n_in; (void)out_size;
}

// round 17
// speedup vs baseline: 1.1279x; 1.0005x over previous
#include <cuda_runtime.h>
#include <cuda_bf16.h>
#include <cuda_fp16.h>
#include <cstdint>

// ---------------- problem constants ----------------
#define NS    4096      // B*T
#define SDIM  512
#define AG    16
#define ACT   20
#define MOUT  320
#define EDIM  64
#define COLS  1216      // 1024 w1 + 64 b1 + 64 wf + 64 zv
#define COLSP 1280      // padded to 8*160

#define LOG2E 1.4426950408889634f
#define LN2   0.6931471805599453f

// ---------------- device scratch ----------------
__device__ __half  g_C[NS * COLS];           // fp16 intermediate (halved traffic)
__device__ __half  g_A0[NS * SDIM];          // fp16(state)
__device__ __half  g_B0[COLSP * SDIM];       // fp16(W)
__device__ float   g_bias[COLSP];

// ---------------- PTX helpers (sm_100-safe) ----------------
__device__ __forceinline__ uint32_t smem_u32(const void* p) {
    uint32_t a;
    asm("{ .reg .u64 t; cvta.to.shared.u64 t, %1; cvt.u32.u64 %0, t; }" : "=r"(a) : "l"(p));
    return a;
}
__device__ __forceinline__ void cp16(uint32_t dst, const void* src) {
    asm volatile("cp.async.cg.shared.global [%0], [%1], 16;" :: "r"(dst), "l"(src));
}
#define CP_COMMIT() asm volatile("cp.async.commit_group;" ::: "memory")
#define CP_WAIT2()  asm volatile("cp.async.wait_group 2;" ::: "memory")

__device__ __forceinline__ void ldm_x4(uint32_t* r, uint32_t addr) {
    asm volatile("ldmatrix.sync.aligned.m8n8.x4.shared.b16 {%0,%1,%2,%3}, [%4];"
        : "=r"(r[0]), "=r"(r[1]), "=r"(r[2]), "=r"(r[3]) : "r"(addr));
}
__device__ __forceinline__ void ldm_x2(uint32_t* r, uint32_t addr) {
    asm volatile("ldmatrix.sync.aligned.m8n8.x2.shared.b16 {%0,%1}, [%2];"
        : "=r"(r[0]), "=r"(r[1]) : "r"(addr));
}
__device__ __forceinline__ void mma_f16(float* c, const uint32_t* a, uint32_t b0, uint32_t b1) {
    asm volatile(
        "mma.sync.aligned.m16n8k16.row.col.f32.f16.f16.f32 "
        "{%0,%1,%2,%3}, {%4,%5,%6,%7}, {%8,%9}, {%0,%1,%2,%3};"
        : "+f"(c[0]), "+f"(c[1]), "+f"(c[2]), "+f"(c[3])
        : "r"(a[0]), "r"(a[1]), "r"(a[2]), "r"(a[3]), "r"(b0), "r"(b1));
}

// ============================================================================
// Kernel 0: A -> fp16; W -> fp16; concat bias. (R8/R12-proven grid shape)
// ============================================================================
__device__ __forceinline__ uint32_t pack2h(float a, float b) {
    __half2 t(__float2half_rn(a), __float2half_rn(b));
    return *(uint32_t*)&t;
}

#define CONV_ABLK 512
#define CONV_BBLK 160
#define CONV_GRID (CONV_ABLK + CONV_BBLK + 5)

__global__ void __launch_bounds__(256)
convert_split(const float* __restrict__ state,
              const float* __restrict__ W_h1, const float* __restrict__ b_h1,
              const float* __restrict__ W_b1, const float* __restrict__ b_b1,
              const float* __restrict__ W_hf, const float* __restrict__ b_hf,
              const float* __restrict__ W_v1, const float* __restrict__ b_v1)
{
    const int blk = blockIdx.x;
    const int tid = threadIdx.x;

    if (blk < CONV_ABLK) {
        int base = blk * 1024 + tid;
        float4 v[4];
        #pragma unroll
        for (int k = 0; k < 4; k++)
            v[k] = ((const float4*)state)[base + k * 256];
        #pragma unroll
        for (int k = 0; k < 4; k++) {
            uint2 p;
            p.x = pack2h(v[k].x, v[k].y);  p.y = pack2h(v[k].z, v[k].w);
            ((uint2*)g_A0)[base + k * 256] = p;
        }
    } else if (blk < CONV_ABLK + CONV_BBLK) {
        int base = (blk - CONV_ABLK) * 1024 + tid;
        float4 v[4];
        #pragma unroll
        for (int k = 0; k < 4; k++) {
            int q = base + k * 256;
            int row = q >> 7;            // 128 quads per 512-wide row
            int cq  = q & 127;
            if (row < 1024)      v[k] = ((const float4*)(W_h1 + (size_t)row * SDIM))[cq];
            else if (row < 1088) v[k] = ((const float4*)(W_b1 + (size_t)(row - 1024) * SDIM))[cq];
            else if (row < 1152) v[k] = ((const float4*)(W_hf + (size_t)(row - 1088) * SDIM))[cq];
            else if (row < 1216) v[k] = ((const float4*)(W_v1 + (size_t)(row - 1152) * SDIM))[cq];
            else                 v[k] = make_float4(0.f, 0.f, 0.f, 0.f);
        }
        #pragma unroll
        for (int k = 0; k < 4; k++) {
            uint2 p;
            p.x = pack2h(v[k].x, v[k].y);  p.y = pack2h(v[k].z, v[k].w);
            ((uint2*)g_B0)[base + k * 256] = p;
        }
    } else {
        int c = (blk - CONV_ABLK - CONV_BBLK) * 256 + tid;
        if (c < COLSP) {
            float b = 0.f;
            if (c < 1024)      b = b_h1[c];
            else if (c < 1088) b = b_b1[c - 1024];
            else if (c < 1152) b = b_hf[c - 1088];
            else if (c < 1216) b = b_v1[c - 1152];
            g_bias[c] = b;
        }
    }
}

// ============================================================================
// Kernel 1: HMMA fp16 GEMM: C = A0*B0 + bias -> fp16 g_C
// Tile 128(M) x 160(N) x 32(K). grid (8, 32) = 256 CTAs, 2 CTAs/SM.
// 4-stage cp.async, lookahead 2, single barrier per k-iter (R8 proof).
// Epilogue packs to half2 (halved store traffic).
// ============================================================================
#define ROWB   80
#define MATBA  (128 * ROWB)             // 10240 B
#define MATBB  (160 * ROWB)             // 12800 B
#define STAGEB (MATBA + MATBB)          // 23040 B
#define NSTAGE 4
#define GEMM_SMEM (NSTAGE * STAGEB)     // 92160 B
#define NCHUNKS ((128 + 160) * 4)       // 1152 16B-chunks per stage

__device__ __forceinline__ void load_stage(uint32_t sb, int tid, int rowA, int rowB, int kt) {
    #pragma unroll
    for (int t = 0; t < 5; t++) {
        int id = tid + t * 256;          // 0..1279
        if (id < NCHUNKS) {
            if (id < 512) {
                int r = id >> 2, c = id & 3;
                cp16(sb + (uint32_t)(r * ROWB + c * 16),
                     (const char*)g_A0 + ((size_t)(rowA + r) * SDIM + kt) * 2 + c * 16);
            } else {
                int q = id - 512;
                int r = q >> 2, c = q & 3;
                cp16(sb + MATBA + (uint32_t)(r * ROWB + c * 16),
                     (const char*)g_B0 + ((size_t)(rowB + r) * SDIM + kt) * 2 + c * 16);
            }
        }
    }
}

__global__ void __launch_bounds__(256, 2)
gemm_tc()
{
    extern __shared__ char smem[];
    const uint32_t sbase = smem_u32(smem);
    const int tid  = threadIdx.x;
    const int wid  = tid >> 5;
    const int lane = tid & 31;
    const int cb   = blockIdx.x;   // 0..7
    const int rb   = blockIdx.y;   // 0..31

    const int warp_m = wid >> 2;
    const int warp_n = wid & 3;
    const int rowA = rb * 128;
    const int rowB = cb * 160;

    float c[4][5][4];
    #pragma unroll
    for (int i = 0; i < 4; i++)
        #pragma unroll
        for (int j = 0; j < 5; j++)
            #pragma unroll
            for (int q = 0; q < 4; q++)
                c[i][j][q] = 0.f;

    load_stage(sbase + 0 * STAGEB, tid, rowA, rowB, 0);
    CP_COMMIT();
    load_stage(sbase + 1 * STAGEB, tid, rowA, rowB, 32);
    CP_COMMIT();

    const uint32_t lrow  = (uint32_t)(lane & 15) * ROWB;
    const uint32_t lcol  = (uint32_t)(lane >> 4) * 16;
    const uint32_t lrow2 = (uint32_t)(lane & 7) * ROWB;
    const uint32_t lcol2 = (uint32_t)((lane >> 3) & 1) * 16;

    const int NK = SDIM / 32;   // 16
    for (int kt = 0; kt < NK; kt++) {
        if (kt + 2 < NK)
            load_stage(sbase + ((kt + 2) % NSTAGE) * STAGEB, tid, rowA, rowB, (kt + 2) * 32);
        CP_COMMIT();
        CP_WAIT2();
        __syncthreads();

        const uint32_t st = sbase + (kt % NSTAGE) * STAGEB;
        const uint32_t aAddr   = st + lrow + lcol;
        const uint32_t bBase   = st + MATBA + (uint32_t)(warp_n * 40) * ROWB;
        const uint32_t bAddrX4 = bBase + lrow + lcol;
        const uint32_t bAddrX2 = bBase + 32 * ROWB + lrow2 + lcol2;

        #pragma unroll
        for (int kk = 0; kk < 2; kk++) {
            uint32_t a[4][4];
            #pragma unroll
            for (int mt = 0; mt < 4; mt++)
                ldm_x4(a[mt], aAddr + (uint32_t)((warp_m * 64 + mt * 16) * ROWB + kk * 32));

            uint32_t b4a[4], b4b[4], b2[2];
            ldm_x4(b4a, bAddrX4 + (uint32_t)(kk * 32));
            ldm_x4(b4b, bAddrX4 + (uint32_t)(16 * ROWB + kk * 32));
            ldm_x2(b2,  bAddrX2 + (uint32_t)(kk * 32));

            #pragma unroll
            for (int mt = 0; mt < 4; mt++) {
                mma_f16(c[mt][0], a[mt], b4a[0], b4a[2]);
                mma_f16(c[mt][1], a[mt], b4a[1], b4a[3]);
                mma_f16(c[mt][2], a[mt], b4b[0], b4b[2]);
                mma_f16(c[mt][3], a[mt], b4b[1], b4b[3]);
                mma_f16(c[mt][4], a[mt], b2[0],  b2[1]);
            }
        }
        // no trailing barrier (stage reuse distance 3 mod 4; see R8)
    }

    // epilogue: bias add (fp32), pack to half2, store 4B per fragment row
    const int rbase = rb * 128 + warp_m * 64 + (lane >> 2);
    const int cbase = cb * 160 + warp_n * 40 + (lane & 3) * 2;
    #pragma unroll
    for (int nt = 0; nt < 5; nt++) {
        int col = cbase + nt * 8;
        if (col >= COLS) continue;
        float2 bias = *(const float2*)(g_bias + col);
        #pragma unroll
        for (int mt = 0; mt < 4; mt++) {
            int r0 = rbase + mt * 16;
            uint32_t p0 = pack2h(c[mt][nt][0] + bias.x, c[mt][nt][1] + bias.y);
            uint32_t p1 = pack2h(c[mt][nt][2] + bias.x, c[mt][nt][3] + bias.y);
            *(uint32_t*)(g_C + (size_t)r0 * COLS + col)       = p0;
            *(uint32_t*)(g_C + (size_t)(r0 + 8) * COLS + col) = p1;
        }
    }
}

// ============================================================================
// Kernel 2: mixer v7. TWO warps per sample, packed-half2 inner loop, agent
// loops unrolled x2 (R16). g_C now fp16: wh/wfh load directly as half2 (no
// cvt in the hot loop); u2 accumulates fp32 from converted half2 pairs.
// ============================================================================
__global__ void __launch_bounds__(256)
mixer(const float* __restrict__ q_agents,
      const int*   __restrict__ actions,
      const float* __restrict__ W_v2,
      const float* __restrict__ b_v2,
      float*       __restrict__ out)
{
    const int gw = (blockIdx.x * blockDim.x + threadIdx.x) >> 5;
    if (gw >= NS * 2) return;
    const int n    = gw >> 1;
    const int half = gw & 1;
    const int lane = threadIdx.x & 31;
    const int eg   = lane >> 2;         // 0..7 -> 8 e-values each
    const int slot = lane & 3;          // 0..3 action slot
    const int e0   = eg * 8;
    const unsigned FULL = 0xffffffffu;

    const __half* Crow = g_C + (size_t)n * COLS;

    float qt_own = 0.f;
    if (lane < AG) {
        int a = actions[n * AG + lane];
        qt_own = q_agents[(size_t)(n * AG + lane) * ACT + a];
    }

    // v = relu(zv) @ W_v2 + b_v2
    float zv0 = __half2float(Crow[1152 + lane]);
    float zv1 = __half2float(Crow[1184 + lane]);
    float vp  = fmaxf(zv0, 0.f) * W_v2[lane] + fmaxf(zv1, 0.f) * W_v2[lane + 32];
    #pragma unroll
    for (int off = 16; off >= 1; off >>= 1)
        vp += __shfl_xor_sync(FULL, vp, off);
    const float v = vp + b_v2[0];

    // u2[e] = b1[e] + sum_j qt[j]*w1[j,e]   (fp32 accumulation from fp16 C)
    float u2[8];
    {
        uint4 t = *(const uint4*)(Crow + 1024 + e0);
        const __half2* h = (const __half2*)&t;
        #pragma unroll
        for (int p = 0; p < 4; p++) {
            float2 f = __half22float2(h[p]);
            u2[2*p] = f.x; u2[2*p+1] = f.y;
        }
    }
    #pragma unroll 2
    for (int i = 0; i < AG; i++) {
        float qti = __shfl_sync(FULL, qt_own, i);
        uint4 t = *(const uint4*)(Crow + i * EDIM + e0);
        const __half2* h = (const __half2*)&t;
        #pragma unroll
        for (int p = 0; p < 4; p++) {
            float2 f = __half22float2(h[p]);
            u2[2*p]   = fmaf(qti, f.x, u2[2*p]);
            u2[2*p+1] = fmaf(qti, f.y, u2[2*p+1]);
        }
    }
    // pack u2 (log2-domain) into half2 pairs
    __half2 u2h[4];
    #pragma unroll
    for (int p = 0; p < 4; p++)
        u2h[p] = __floats2half2_rn(u2[2*p] * LOG2E, u2[2*p+1] * LOG2E);

    // wf slice: half2 pairs directly + fp32 sum (exact -1 fold)
    float swf = 0.f;
    __half2 wfh[4];
    {
        uint4 t = *(const uint4*)(Crow + 1088 + e0);
        const __half2* h = (const __half2*)&t;
        #pragma unroll
        for (int p = 0; p < 4; p++) {
            wfh[p] = h[p];
            float2 f = __half22float2(h[p]);
            swf += f.x + f.y;
        }
    }

    const __half2 z2 = __float2half2_rn(0.f);

    const int i0 = half * 8;
    #pragma unroll 2
    for (int i = i0; i < i0 + 8; i++) {
        __half2 wh[4];
        {
            uint4 t = *(const uint4*)(Crow + i * EDIM + e0);
            const __half2* h = (const __half2*)&t;
            wh[0] = h[0]; wh[1] = h[1]; wh[2] = h[2]; wh[3] = h[3];
        }
        float qti = __shfl_sync(FULL, qt_own, i);
        const float* qrow = q_agents + (size_t)(n * AG + i) * ACT;

        float qv[5];
        #pragma unroll
        for (int r = 0; r < 5; r++) qv[r] = qrow[r * 4 + slot];

        #pragma unroll
        for (int r = 0; r < 5; r++) {
            int act = r * 4 + slot;
            float deltaL = (qv[r] - qti) * LOG2E;
            __half2 dL2 = __float2half2_rn(deltaL);

            __half2 acc1h = z2, acc2h = z2;
            #pragma unroll
            for (int p = 0; p < 4; p++) {
                __half2 xh = __hfma2(dL2, wh[p], u2h[p]);
                acc1h = __hfma2(__hmax2(xh, z2), wfh[p], acc1h);
                acc2h = __hfma2(h2exp2(__hmin2(xh, z2)), wfh[p], acc2h);
            }
            float2 a1 = __half22float2(acc1h);
            float2 a2 = __half22float2(acc2h);
            float accv = fmaf(a1.x + a1.y, LN2, a2.x + a2.y) - swf;
            accv += __shfl_xor_sync(FULL, accv, 4);
            accv += __shfl_xor_sync(FULL, accv, 8);
            accv += __shfl_xor_sync(FULL, accv, 16);
            if (eg == 0)
                out[(size_t)n * MOUT + i * ACT + act] = accv + v;
        }
    }
}

// ============================================================================
extern "C" void kernel_launch(void* const* d_in, const int* in_sizes, int n_in,
                              void* d_out, int out_size) {
    const float* q_agents = (const float*)d_in[0];
    const int*   actions  = (const int*)d_in[1];
    const float* state    = (const float*)d_in[2];
    const float* W_h1 = (const float*)d_in[3];
    const float* b_h1 = (const float*)d_in[4];
    const float* W_b1 = (const float*)d_in[5];
    const float* b_b1 = (const float*)d_in[6];
    const float* W_hf = (const float*)d_in[7];
    const float* b_hf = (const float*)d_in[8];
    const float* W_v1 = (const float*)d_in[9];
    const float* b_v1 = (const float*)d_in[10];
    const float* W_v2 = (const float*)d_in[11];
    const float* b_v2 = (const float*)d_in[12];
    float* out = (float*)d_out;

    cudaFuncSetAttribute(gemm_tc, cudaFuncAttributeMaxDynamicSharedMemorySize, GEMM_SMEM);

    convert_split<<<CONV_GRID, 256>>>(
        state, W_h1, b_h1, W_b1, b_b1, W_hf, b_hf, W_v1, b_v1);

    dim3 g1(8, 32);
    gemm_tc<<<g1, 256, GEMM_SMEM>>>();

    mixer<<<(NS * 2 * 32 + 255) / 256, 256>>>(q_agents, actions, W_v2, b_v2, out);
    (void)in_sizes; (void)n_in; (void)out_size;
}